// round 10
// baseline (speedup 1.0000x reference)
#include <cuda_runtime.h>

// sim = dot(f, m[idx]) / ((||f||+eps)*(||m[idx]||+eps)); bucket 0/1/2 -> float32 out.
// Dataset: N=100000, C=10000, D=768. Inputs identified BY SIZE (order-proof).
//
// LTS-cap analysis: warp-per-row gather pays 2x307MB through L2 (feats stream +
// mem gather) = the chip LTS ceiling. This version groups rows by center:
// block-per-center loads m_c into SMEM once, so the mem gather costs ~31MB of
// LTS instead of 307MB; the kernel becomes DRAM-bound on the feats stream.

#define MAX_C   10240
#define CAP     24          // bucket slots per center; Poisson(10) overflow -> list
#define OVFB    128         // tail blocks for overflow rows
#define THREADS 256         // 8 warps

__device__ int   g_cnt[MAX_C];
__device__ int   g_bucket[MAX_C * CAP];
__device__ int   g_ovf[100000];
__device__ int   g_ovfcnt;

__global__ void zero_kernel(int C) {
    int i = blockIdx.x * blockDim.x + threadIdx.x;
    if (i < C) g_cnt[i] = 0;
    if (i == 0) g_ovfcnt = 0;
}

__global__ void scatter_kernel(const int* __restrict__ idx, int N, int C) {
    int i = blockIdx.x * blockDim.x + threadIdx.x;
    if (i >= N) return;
    int c = idx[i];
    c = min(max(c, 0), C - 1);
    int s = atomicAdd(&g_cnt[c], 1);
    if (s < CAP) g_bucket[c * CAP + s] = i;
    else         g_ovf[atomicAdd(&g_ovfcnt, 1)] = i;
}

__device__ __forceinline__ float3 warp_dot_nf_nm_gs(const float4* f4, const float4* m4s) {
    // f4: gmem row base (+lane), m4s: smem row base (+lane). 6 iters, D=768.
    int lane = threadIdx.x & 31;
    float dot = 0.f, nf = 0.f, nm = 0.f;
    #pragma unroll
    for (int j = 0; j < 6; j++) {
        float4 a = __ldcs(f4 + j * 32 + lane);
        float4 b = m4s[j * 32 + lane];
        dot += a.x*b.x + a.y*b.y + a.z*b.z + a.w*b.w;
        nf  += a.x*a.x + a.y*a.y + a.z*a.z + a.w*a.w;
        nm  += b.x*b.x + b.y*b.y + b.z*b.z + b.w*b.w;
    }
    #pragma unroll
    for (int o = 16; o > 0; o >>= 1) {
        dot += __shfl_xor_sync(0xffffffffu, dot, o);
        nf  += __shfl_xor_sync(0xffffffffu, nf, o);
        nm  += __shfl_xor_sync(0xffffffffu, nm, o);
    }
    return make_float3(dot, nf, nm);
}

__global__ __launch_bounds__(THREADS)
void main_grouped(const float* __restrict__ feats,
                  const float* __restrict__ mem,
                  const int* __restrict__ idx,
                  float* __restrict__ out,
                  int N, int C) {
    __shared__ float4 m_s[192];   // one center row, 3KB
    int bid = blockIdx.x;
    int wid = threadIdx.x >> 5;
    int lane = threadIdx.x & 31;

    if (bid < C) {
        // ---- center block: rows sharing center bid ----
        int cnt = g_cnt[bid];
        if (cnt == 0) return;
        int nb = min(cnt, CAP);
        // cooperative smem load of m_c (192 float4)
        const float4* m4 = reinterpret_cast<const float4*>(mem) + (size_t)bid * 192;
        if (threadIdx.x < 192) m_s[threadIdx.x] = __ldg(m4 + threadIdx.x);
        __syncthreads();

        for (int w = wid; w < nb; w += 8) {
            int row = g_bucket[bid * CAP + w];
            const float4* f4 = reinterpret_cast<const float4*>(feats) + (size_t)row * 192;
            float3 r = warp_dot_nf_nm_gs(f4, m_s);
            if (lane == 0) {
                float sim = r.x / ((sqrtf(r.y) + 1e-12f) * (sqrtf(r.z) + 1e-12f));
                out[row] = (sim >= 0.6f) ? 0.0f : ((sim >= 0.4f) ? 1.0f : 2.0f);
            }
        }
    } else {
        // ---- overflow tail: generic warp-per-row straight from L2 ----
        int nov = g_ovfcnt;
        if (nov > N) nov = N;
        int wslot = (bid - C) * 8 + wid;
        for (int i = wslot; i < nov; i += OVFB * 8) {
            int row = g_ovf[i];
            int c = idx[row];
            c = min(max(c, 0), C - 1);
            const float4* f4 = reinterpret_cast<const float4*>(feats) + (size_t)row * 192;
            const float4* m4 = reinterpret_cast<const float4*>(mem) + (size_t)c * 192;
            float dot = 0.f, nf = 0.f, nm = 0.f;
            #pragma unroll
            for (int j = 0; j < 6; j++) {
                float4 a = __ldcs(f4 + j * 32 + lane);
                float4 b = __ldg(m4 + j * 32 + lane);
                dot += a.x*b.x + a.y*b.y + a.z*b.z + a.w*b.w;
                nf  += a.x*a.x + a.y*a.y + a.z*a.z + a.w*a.w;
                nm  += b.x*b.x + b.y*b.y + b.z*b.z + b.w*b.w;
            }
            #pragma unroll
            for (int o = 16; o > 0; o >>= 1) {
                dot += __shfl_xor_sync(0xffffffffu, dot, o);
                nf  += __shfl_xor_sync(0xffffffffu, nf, o);
                nm  += __shfl_xor_sync(0xffffffffu, nm, o);
            }
            if (lane == 0) {
                float sim = dot / ((sqrtf(nf) + 1e-12f) * (sqrtf(nm) + 1e-12f));
                out[row] = (sim >= 0.6f) ? 0.0f : ((sim >= 0.4f) ? 1.0f : 2.0f);
            }
        }
    }
}

// Generic fallback (any D multiple of 4) — used if shape differs from dataset.
__global__ void sim_bucket_generic(const float* __restrict__ feats,
                                   const float* __restrict__ mem,
                                   const int* __restrict__ idx,
                                   float* __restrict__ out,
                                   int N, int C, int D) {
    int row = blockIdx.x * 8 + (threadIdx.x >> 5);
    int lane = threadIdx.x & 31;
    if (row >= N) return;
    int c = idx[row];
    c = min(max(c, 0), C - 1);
    const float4* f = reinterpret_cast<const float4*>(feats + (size_t)row * D);
    const float4* m = reinterpret_cast<const float4*>(mem + (size_t)c * D);
    int nvec = D >> 2;
    float dot = 0.f, nf = 0.f, nm = 0.f;
    for (int j = lane; j < nvec; j += 32) {
        float4 a = f[j], b = __ldg(&m[j]);
        dot += a.x*b.x + a.y*b.y + a.z*b.z + a.w*b.w;
        nf  += a.x*a.x + a.y*a.y + a.z*a.z + a.w*a.w;
        nm  += b.x*b.x + b.y*b.y + b.z*b.z + b.w*b.w;
    }
    #pragma unroll
    for (int o = 16; o > 0; o >>= 1) {
        dot += __shfl_xor_sync(0xffffffffu, dot, o);
        nf  += __shfl_xor_sync(0xffffffffu, nf, o);
        nm  += __shfl_xor_sync(0xffffffffu, nm, o);
    }
    if (lane == 0) {
        float sim = dot / ((sqrtf(nf) + 1e-12f) * (sqrtf(nm) + 1e-12f));
        out[row] = (sim >= 0.6f) ? 0.0f : ((sim >= 0.4f) ? 1.0f : 2.0f);
    }
}

extern "C" void kernel_launch(void* const* d_in, const int* in_sizes, int n_in,
                              void* d_out, int out_size) {
    // Identify inputs by element count: idx=smallest, feats=largest, memory=middle.
    int pi = 0, pf = 0;
    for (int i = 1; i < 3; i++) {
        if (in_sizes[i] < in_sizes[pi]) pi = i;
        if (in_sizes[i] > in_sizes[pf]) pf = i;
    }
    int pm = 3 - pi - pf;

    const int*   idx   = (const int*)d_in[pi];
    const float* feats = (const float*)d_in[pf];
    const float* mem   = (const float*)d_in[pm];

    int N = in_sizes[pi];        // 100000
    int D = in_sizes[pf] / N;    // 768
    int C = in_sizes[pm] / D;    // 10000

    float* out = (float*)d_out;  // [N] float32

    if (D == 768 && C <= MAX_C) {
        zero_kernel<<<(C + THREADS - 1) / THREADS, THREADS>>>(C);
        scatter_kernel<<<(N + THREADS - 1) / THREADS, THREADS>>>(idx, N, C);
        main_grouped<<<C + OVFB, THREADS>>>(feats, mem, idx, out, N, C);
    } else {
        sim_bucket_generic<<<(N + 7) / 8, THREADS>>>(feats, mem, idx, out, N, C, D);
    }
}

// round 11
// speedup vs baseline: 1.0835x; 1.0835x over previous
#include <cuda_runtime.h>

// sim = dot(f, m[idx]) / ((||f||+eps)*(||m[idx]||+eps)); bucket 0/1/2 -> float32 out.
// Dataset: N=100000, C=10000, D=768. Inputs identified BY SIZE (order-proof).
// DRAM-bound (338MB ideal traffic, mem[] L2-resident). Fused single kernel;
// each warp does 2 rows with all 12 DRAM loads front-batched to double MLP.

#define WPB 8
#define THREADS (WPB * 32)

__device__ __forceinline__ float3 warp_red3(float dot, float nf, float nm) {
    #pragma unroll
    for (int o = 16; o > 0; o >>= 1) {
        dot += __shfl_xor_sync(0xffffffffu, dot, o);
        nf  += __shfl_xor_sync(0xffffffffu, nf, o);
        nm  += __shfl_xor_sync(0xffffffffu, nm, o);
    }
    return make_float3(dot, nf, nm);
}

__device__ __forceinline__ void finish(float* __restrict__ out, int row, float3 r) {
    float sim = r.x / ((sqrtf(r.y) + 1e-12f) * (sqrtf(r.z) + 1e-12f));
    out[row] = (sim >= 0.6f) ? 0.0f : ((sim >= 0.4f) ? 1.0f : 2.0f);
}

__global__ __launch_bounds__(THREADS, 3)
void sim_bucket_fused2(const float* __restrict__ feats,
                       const float* __restrict__ mem,
                       const int* __restrict__ idx,
                       float* __restrict__ out,
                       int N, int C) {
    int w = blockIdx.x * WPB + (threadIdx.x >> 5);   // global warp id
    int lane = threadIdx.x & 31;
    int row0 = 2 * w;
    int row1 = 2 * w + 1;
    if (row0 >= N) return;
    bool has1 = (row1 < N);

    int c0 = idx[row0];
    int c1 = has1 ? idx[row1] : c0;
    c0 = min(max(c0, 0), C - 1);
    c1 = min(max(c1, 0), C - 1);

    const float4* f0 = reinterpret_cast<const float4*>(feats) + (size_t)row0 * 192 + lane;
    const float4* f1 = reinterpret_cast<const float4*>(feats) + (size_t)row1 * 192 + lane;
    const float4* m0 = reinterpret_cast<const float4*>(mem)   + (size_t)c0   * 192 + lane;
    const float4* m1 = reinterpret_cast<const float4*>(mem)   + (size_t)c1   * 192 + lane;
    if (!has1) f1 = f0;  // harmless re-read; result discarded

    // Phase 1: all 12 DRAM (feats) loads in flight — these carry the ~600cyc latency.
    float4 a00 = __ldcs(f0);        float4 a01 = __ldcs(f0 + 32);
    float4 a02 = __ldcs(f0 + 64);   float4 a03 = __ldcs(f0 + 96);
    float4 a04 = __ldcs(f0 + 128);  float4 a05 = __ldcs(f0 + 160);
    float4 a10 = __ldcs(f1);        float4 a11 = __ldcs(f1 + 32);
    float4 a12 = __ldcs(f1 + 64);   float4 a13 = __ldcs(f1 + 96);
    float4 a14 = __ldcs(f1 + 128);  float4 a15 = __ldcs(f1 + 160);

    // Phase 2: L2-resident mem loads for row0, consumed immediately (short latency).
    float dot0 = 0.f, nf0 = 0.f, nm0 = 0.f;
    {
        float4 b;
        #define ACC0(A, OFF)                                        \
            b = __ldg(m0 + OFF);                                    \
            dot0 += A.x*b.x + A.y*b.y + A.z*b.z + A.w*b.w;          \
            nf0  += A.x*A.x + A.y*A.y + A.z*A.z + A.w*A.w;          \
            nm0  += b.x*b.x + b.y*b.y + b.z*b.z + b.w*b.w;
        ACC0(a00, 0) ACC0(a01, 32) ACC0(a02, 64)
        ACC0(a03, 96) ACC0(a04, 128) ACC0(a05, 160)
        #undef ACC0
    }
    float dot1 = 0.f, nf1 = 0.f, nm1 = 0.f;
    {
        float4 b;
        #define ACC1(A, OFF)                                        \
            b = __ldg(m1 + OFF);                                    \
            dot1 += A.x*b.x + A.y*b.y + A.z*b.z + A.w*b.w;          \
            nf1  += A.x*A.x + A.y*A.y + A.z*A.z + A.w*A.w;          \
            nm1  += b.x*b.x + b.y*b.y + b.z*b.z + b.w*b.w;
        ACC1(a10, 0) ACC1(a11, 32) ACC1(a12, 64)
        ACC1(a13, 96) ACC1(a14, 128) ACC1(a15, 160)
        #undef ACC1
    }

    float3 r0 = warp_red3(dot0, nf0, nm0);
    float3 r1 = warp_red3(dot1, nf1, nm1);
    if (lane == 0) {
        finish(out, row0, r0);
        if (has1) finish(out, row1, r1);
    }
}

// Generic fallback (any D multiple of 4) — used if shape differs from dataset.
__global__ void sim_bucket_generic(const float* __restrict__ feats,
                                   const float* __restrict__ mem,
                                   const int* __restrict__ idx,
                                   float* __restrict__ out,
                                   int N, int C, int D) {
    int row = blockIdx.x * WPB + (threadIdx.x >> 5);
    int lane = threadIdx.x & 31;
    if (row >= N) return;
    int c = idx[row];
    c = min(max(c, 0), C - 1);
    const float4* f = reinterpret_cast<const float4*>(feats + (size_t)row * D);
    const float4* m = reinterpret_cast<const float4*>(mem + (size_t)c * D);
    int nvec = D >> 2;
    float dot = 0.f, nf = 0.f, nm = 0.f;
    for (int j = lane; j < nvec; j += 32) {
        float4 a = f[j], b = __ldg(&m[j]);
        dot += a.x*b.x + a.y*b.y + a.z*b.z + a.w*b.w;
        nf  += a.x*a.x + a.y*a.y + a.z*a.z + a.w*a.w;
        nm  += b.x*b.x + b.y*b.y + b.z*b.z + b.w*b.w;
    }
    float3 r = warp_red3(dot, nf, nm);
    if (lane == 0) finish(out, row, r);
}

extern "C" void kernel_launch(void* const* d_in, const int* in_sizes, int n_in,
                              void* d_out, int out_size) {
    // Identify inputs by element count: idx=smallest, feats=largest, memory=middle.
    int pi = 0, pf = 0;
    for (int i = 1; i < 3; i++) {
        if (in_sizes[i] < in_sizes[pi]) pi = i;
        if (in_sizes[i] > in_sizes[pf]) pf = i;
    }
    int pm = 3 - pi - pf;

    const int*   idx   = (const int*)d_in[pi];
    const float* feats = (const float*)d_in[pf];
    const float* mem   = (const float*)d_in[pm];

    int N = in_sizes[pi];        // 100000
    int D = in_sizes[pf] / N;    // 768
    int C = in_sizes[pm] / D;    // 10000

    float* out = (float*)d_out;  // [N] float32

    if (D == 768) {
        int nwarp = (N + 1) / 2;                       // 2 rows per warp
        int grid = (nwarp + WPB - 1) / WPB;
        sim_bucket_fused2<<<grid, THREADS>>>(feats, mem, idx, out, N, C);
    } else {
        sim_bucket_generic<<<(N + WPB - 1) / WPB, THREADS>>>(feats, mem, idx, out, N, C, D);
    }
}